// round 9
// baseline (speedup 1.0000x reference)
#include <cuda_runtime.h>
#include <cstdint>

typedef unsigned long long ull;

// ---------------- problem constants ----------------
#define NPART 32
#define L0 (2048*1024)
#define L1 2048
#define L2 (256*2048)
#define L3 256
#define SEG_B0 (L0)              // 2097152
#define SEG_B1 (SEG_B0 + L1)     // 2099200
#define SEG_B2 (SEG_B1 + L2)     // 2623488
#define P_TOT  (SEG_B2 + L3)     // 2623744
#define EPSV 0.1f

// ---- gram: chunks of 512 k (last = 256 k) ----
#define GCH 512
#define GNCH 5125
#define GROW_B 2048
#define GSTAGES 3
#define GSTAGE_B (32*GROW_B)     // 65536
#define GOFF 1024
#define GSMEM (GOFF + GSTAGES*GSTAGE_B)   // 197632
#define NBLK1 148
#define NWARP1 20
#define GTHREADS 640
#define GPW 19                   // producer warp (highest priority)

// ---- apply: chunks of 256 k (10249 exact, no tail) ----
#define ACH 256
#define ANCH (P_TOT/ACH)         // 10249
#define AROW_B 1024
#define ASTAGES 3
#define ASTAGE_B (32*AROW_B)     // 32768
#define AOFF 9216                // mbar(64) + cf table(8KB) before stages
#define ASMEM (AOFF + ASTAGES*ASTAGE_B)   // 107520 -> 2 CTAs/SM
#define NBLK2 296
#define ATHREADS 512
#define APW 15                   // producer warp

// ---------------- scratch ----------------
__device__ float  g_Gpart[NBLK1 * NWARP1 * 32];
__device__ float2 g_Cd[1024];        // g_Cd[j*32+i] = (C[i][j], C[i][j])

// gram tile map: warp w computes rows [TI*4, TI*4+4) x cols [TJ*8, TJ*8+8)
__constant__ int c_TI[NWARP1] = {0,1,0,1,2,3,0,1,2,3,4,5,0,1,2,3,4,5,6,7};
__constant__ int c_TJ[NWARP1] = {0,0,1,1,1,1,2,2,2,2,2,2,3,3,3,3,3,3,3,3};

// ---------------- PTX helpers ----------------
__device__ __forceinline__ void ffma2(ull &d, ull a, ull b) {
    asm("fma.rn.f32x2 %0, %1, %2, %0;" : "+l"(d) : "l"(a), "l"(b));
}
__device__ __forceinline__ void mbar_init(uint32_t mbar, uint32_t cnt) {
    asm volatile("mbarrier.init.shared.b64 [%0], %1;" :: "r"(mbar), "r"(cnt) : "memory");
}
__device__ __forceinline__ void mbar_expect_tx(uint32_t mbar, uint32_t bytes) {
    asm volatile("mbarrier.arrive.expect_tx.shared.b64 _, [%0], %1;"
                 :: "r"(mbar), "r"(bytes) : "memory");
}
__device__ __forceinline__ void mbar_wait(uint32_t mbar, uint32_t phase) {
    asm volatile(
        "{\n\t.reg .pred P;\n\t"
        "WL_%=:\n\t"
        "mbarrier.try_wait.parity.acquire.cta.shared::cta.b64 P, [%0], %1, 0x989680;\n\t"
        "@!P bra WL_%=;\n\t}"
        :: "r"(mbar), "r"(phase) : "memory");
}
__device__ __forceinline__ void bulk_g2s(uint32_t dst, const void* src,
                                         uint32_t bytes, uint32_t mbar) {
    asm volatile(
        "cp.async.bulk.shared::cluster.global.mbarrier::complete_tx::bytes [%0], [%1], %2, [%3];"
        :: "r"(dst), "l"(src), "r"(bytes), "r"(mbar) : "memory");
}

__device__ __forceinline__ const float* seg_base(int k,
        const float* __restrict__ W1, const float* __restrict__ b1,
        const float* __restrict__ W2, const float* __restrict__ b2,
        int &stride, int &kl) {
    if (k < SEG_B0) { stride = L0; kl = k;          return W1; }
    if (k < SEG_B1) { stride = L1; kl = k - SEG_B0; return b1; }
    if (k < SEG_B2) { stride = L2; kl = k - SEG_B1; return W2; }
    stride = L3; kl = k - SEG_B2; return b2;
}

// ---------------- pass 1: Gram (4x8 tiles, 20 warps) ----------------
__global__ __launch_bounds__(GTHREADS, 1)
void gram_kernel(const float* __restrict__ W1, const float* __restrict__ b1,
                 const float* __restrict__ W2, const float* __restrict__ b2) {
    extern __shared__ char sm[];
    const uint32_t sb = (uint32_t)__cvta_generic_to_shared(sm);
    const uint32_t mb_full = sb;
    const int tid  = threadIdx.x;
    const int w    = tid >> 5;
    const int lane = tid & 31;
    const int bi = c_TI[w], bj = c_TJ[w];

    const int per = GNCH / NBLK1, rem = GNCH % NBLK1;
    const int b   = blockIdx.x;
    const int c0  = b * per + (b < rem ? b : rem);
    const int cnt = per + (b < rem ? 1 : 0);

    if (tid == 0) {
#pragma unroll
        for (int s = 0; s < GSTAGES; s++) mbar_init(mb_full + s * 8, 1);
    }
    __syncthreads();

    auto load_chunk = [&](int n) {                // producer warp, lane-parallel
        const int chunk = c0 + n;
        const int buf = n % GSTAGES;
        const uint32_t bytes = (chunk == GNCH - 1) ? 1024u : 2048u;
        int stride, kl;
        const float* base = seg_base(chunk * GCH, W1, b1, W2, b2, stride, kl);
        const uint32_t full = mb_full + buf * 8;
        if (lane == 0) mbar_expect_tx(full, bytes * 32);
        __syncwarp();
        bulk_g2s(sb + GOFF + buf * GSTAGE_B + lane * GROW_B,
                 base + (size_t)lane * stride + kl, bytes, full);
    };

    if (w == GPW) {
        for (int n = 0; n < GSTAGES - 1 && n < cnt; n++) load_chunk(n);
    }

    ull acc[32];
#pragma unroll
    for (int p = 0; p < 32; p++) acc[p] = 0ull;

    int stg = 0, ph = 0;
    for (int it = 0; it < cnt; it++) {
        __syncthreads();
        if (w == GPW) {
            int n = it + GSTAGES - 1;
            if (n < cnt) load_chunk(n);
        }
        mbar_wait(mb_full + stg * 8, ph);

        const char* tb = sm + GOFF + stg * GSTAGE_B;
        const int niter = (c0 + it == GNCH - 1) ? 2 : 4;
        for (int g = 0; g < niter; g++) {
            const char* tg = tb + g * 512 + lane * 16;
            ulonglong2 av[4];
#pragma unroll
            for (int r = 0; r < 4; r++)
                av[r] = *reinterpret_cast<const ulonglong2*>(tg + (bi * 4 + r) * GROW_B);
            ulonglong2 bv = *reinterpret_cast<const ulonglong2*>(tg + (bj * 8) * GROW_B);
#pragma unroll
            for (int q = 0; q < 8; q++) {
                ulonglong2 bvn;
                if (q < 7)
                    bvn = *reinterpret_cast<const ulonglong2*>(tg + (bj * 8 + q + 1) * GROW_B);
#pragma unroll
                for (int r = 0; r < 4; r++) {
                    ffma2(acc[r * 8 + q], av[r].x, bv.x);
                    ffma2(acc[r * 8 + q], av[r].y, bv.y);
                }
                bv = bvn;
            }
        }
        if (++stg == GSTAGES) { stg = 0; ph ^= 1; }
    }

#pragma unroll
    for (int p = 0; p < 32; p++) {
        float v = __uint_as_float((unsigned)acc[p]) +
                  __uint_as_float((unsigned)(acc[p] >> 32));
        v += __shfl_xor_sync(0xffffffffu, v, 16);
        v += __shfl_xor_sync(0xffffffffu, v, 8);
        v += __shfl_xor_sync(0xffffffffu, v, 4);
        v += __shfl_xor_sync(0xffffffffu, v, 2);
        v += __shfl_xor_sync(0xffffffffu, v, 1);
        if (lane == 0) g_Gpart[(b * NWARP1 + w) * 32 + p] = v;
    }
}

// ---------------- pass 1b: partials -> K -> coefficient table ----------------
__global__ __launch_bounds__(1024, 1)
void coef_kernel() {
    __shared__ float Gs[32][32];
    __shared__ float Ks[32][33];
    __shared__ float Ssh[32];
    const int tid = threadIdx.x;

    if (tid < NWARP1 * 32) {
        float s0 = 0.f, s1 = 0.f, s2 = 0.f, s3 = 0.f;
#pragma unroll 1
        for (int bb = 0; bb < NBLK1; bb += 4) {
            s0 += g_Gpart[(bb + 0) * (NWARP1 * 32) + tid];
            s1 += g_Gpart[(bb + 1) * (NWARP1 * 32) + tid];
            s2 += g_Gpart[(bb + 2) * (NWARP1 * 32) + tid];
            s3 += g_Gpart[(bb + 3) * (NWARP1 * 32) + tid];
        }
        float s = (s0 + s1) + (s2 + s3);
        int w = tid >> 5, p = tid & 31, r = p >> 3, q = p & 7;
        Gs[c_TI[w] * 4 + r][c_TJ[w] * 8 + q] = s;
    }
    __syncthreads();
    {   // mirror entries not covered by any tile: I > 2J+1
        int i = tid >> 5, j = tid & 31;
        if ((i >> 2) > 2 * (j >> 3) + 1) Gs[i][j] = Gs[j][i];
    }
    __syncthreads();
    {
        int i = tid >> 5, j = tid & 31;
        float d2 = Gs[i][i] + Gs[j][j] - 2.f * Gs[i][j];
        d2 = fmaxf(d2, 0.f);
        Ks[i][j] = expf(-0.5f * d2);
    }
    __syncthreads();
    if (tid < 32) {
        float s = 0.f;
        for (int j = 1; j < 32; j++) s += Ks[tid][j];
        Ssh[tid] = s;
    }
    __syncthreads();
    {
        int i = tid >> 5, j = tid & 31;
        float v = (j >= 1) ? (EPSV / (float)NPART) * Ks[i][j] : 0.f;
        if (j == i) v += 1.f - 3.f * EPSV * Ssh[i] / (float)NPART;
        g_Cd[j * 32 + i] = make_float2(v, v);   // [j][i], duplicated
    }
}

// ---------------- pass 2: out = C @ theta ----------------
// 2 CTAs/SM x 16 warps; warp w = k in [16w, 16w+16); lane = particle i.
// Coef (c,c) pairs read from smem once per j (conflict-free LDS.64).
__global__ __launch_bounds__(ATHREADS, 2)
void apply_kernel(const float* __restrict__ W1, const float* __restrict__ b1,
                  const float* __restrict__ W2, const float* __restrict__ b2,
                  float* __restrict__ out) {
    extern __shared__ char sm[];
    const uint32_t sb = (uint32_t)__cvta_generic_to_shared(sm);
    const uint32_t mb_full = sb;
    ull* cs = reinterpret_cast<ull*>(sm + 64);    // 1024 x 8B coef table [j*32+i]
    const int tid  = threadIdx.x;
    const int w    = tid >> 5;
    const int lane = tid & 31;

    if (tid == 0) {
#pragma unroll
        for (int s = 0; s < ASTAGES; s++) mbar_init(mb_full + s * 8, 1);
    }
    const ull* cg = reinterpret_cast<const ull*>(g_Cd);
    for (int idx = tid; idx < 1024; idx += ATHREADS) cs[idx] = cg[idx];
    __syncthreads();

    const int per = ANCH / NBLK2, rem = ANCH % NBLK2;
    const int b   = blockIdx.x;
    const int s0  = b * per + (b < rem ? b : rem);
    const int cnt = per + (b < rem ? 1 : 0);

    auto load_chunk = [&](int n) {                // producer warp, lane-parallel
        const int buf = n % ASTAGES;
        int stride, kl;
        const float* base = seg_base((s0 + n) * ACH, W1, b1, W2, b2, stride, kl);
        const uint32_t full = mb_full + buf * 8;
        if (lane == 0) mbar_expect_tx(full, 32 * 1024u);
        __syncwarp();
        bulk_g2s(sb + AOFF + buf * ASTAGE_B + lane * AROW_B,
                 base + (size_t)lane * stride + kl, 1024u, full);
    };

    if (w == APW) {
        for (int n = 0; n < ASTAGES - 1 && n < cnt; n++) load_chunk(n);
    }

    const int sc = tid & 15;            // drain: unit within row (stride 16)
    const int sr = tid >> 4;            // drain: particle row (0..31)

    int stg = 0, ph = 0;
    for (int it = 0; it < cnt; it++) {
        __syncthreads();
        if (w == APW) {
            int n = it + ASTAGES - 1;
            if (n < cnt) load_chunk(n);
        }
        mbar_wait(mb_full + stg * 8, ph);

        char* tb = sm + AOFF + stg * ASTAGE_B;
        const char* tbw = tb + w * 64;            // warp's 16-k window

        ull acc[8];
#pragma unroll
        for (int p = 0; p < 8; p++) acc[p] = 0ull;

#pragma unroll
        for (int j = 0; j < 32; j++) {
            const ulonglong2* pv = reinterpret_cast<const ulonglong2*>(tbw + j * AROW_B);
            ull c = cs[j * 32 + lane];
            ulonglong2 v0 = pv[0], v1 = pv[1];
            ffma2(acc[0], c, v0.x);
            ffma2(acc[1], c, v0.y);
            ffma2(acc[2], c, v1.x);
            ffma2(acc[3], c, v1.y);
            ulonglong2 v2 = pv[2], v3 = pv[3];
            ffma2(acc[4], c, v2.x);
            ffma2(acc[5], c, v2.y);
            ffma2(acc[6], c, v3.x);
            ffma2(acc[7], c, v3.y);
        }

        __syncthreads();                          // all reads of tb done
        {   // transpose: lane = particle row; XOR swizzle on low-3 unit bits
            ulonglong2* row = reinterpret_cast<ulonglong2*>(tb + lane * AROW_B);
#pragma unroll
            for (int m = 0; m < 4; m++) {
                int ulog = w * 4 + m;
                int u = (ulog & ~7) | ((ulog & 7) ^ (lane & 7));
                row[u] = make_ulonglong2(acc[2 * m], acc[2 * m + 1]);
            }
        }
        __syncthreads();
        {   // drain: 16 threads per particle row, 256B-contiguous stores
            const ulonglong2* row = reinterpret_cast<const ulonglong2*>(tb + sr * AROW_B);
            float* op = out + (size_t)sr * P_TOT + (size_t)(s0 + it) * ACH;
#pragma unroll
            for (int t = 0; t < 4; t++) {
                int u = sc + 16 * t;
                ulonglong2 v = row[(u & ~7) | ((u & 7) ^ (sr & 7))];
                *reinterpret_cast<ulonglong2*>(op + 4 * u) = v;
            }
        }
        if (++stg == ASTAGES) { stg = 0; ph ^= 1; }
    }
}

// ---------------- launch ----------------
extern "C" void kernel_launch(void* const* d_in, const int* in_sizes, int n_in,
                              void* d_out, int out_size) {
    const float* W1 = (const float*)d_in[0];
    const float* b1 = (const float*)d_in[1];
    const float* W2 = (const float*)d_in[2];
    const float* b2 = (const float*)d_in[3];
    float* out = (float*)d_out;

    cudaFuncSetAttribute(gram_kernel,  cudaFuncAttributeMaxDynamicSharedMemorySize, GSMEM);
    cudaFuncSetAttribute(apply_kernel, cudaFuncAttributeMaxDynamicSharedMemorySize, ASMEM);

    gram_kernel<<<NBLK1, GTHREADS, GSMEM>>>(W1, b1, W2, b2);
    coef_kernel<<<1, 1024>>>();
    apply_kernel<<<NBLK2, ATHREADS, ASMEM>>>(W1, b1, W2, b2, out);
}